// round 4
// baseline (speedup 1.0000x reference)
#include <cuda_runtime.h>

// tanhP1 bitstream stencil — zero-halo full-T walk.
// out[t] = n5 * x[t-8]:
//   n1 = x[t]*x[t-4]
//   n2 = 1 - n1*c2[t]
//   n3 = 1 - n2*c3[t]*n1[t-1]
//   n4 = 1 - n3*c4[t]*n1[t-2]
//   n5 = 1 - n4*c5[t]*n1[t-3]
// Exact {0,1} floats -> FFMA arithmetic is bit-exact.
//
// Round-4 changes vs round-3:
//  * each thread walks the FULL T=256 (no t-chunking) -> zero halo re-read,
//    traffic drops 544 MB -> 512 MB (the compulsory minimum)
//  * 128-thread blocks -> 1024 blocks, all co-resident (no wave quantization)
//  * __ldcs / __stcs streaming hints (every byte touched exactly once)
//  * keeps float2 columns + MLP=8 front-batched loads from round-3

#define TT 256

__global__ __launch_bounds__(128)
void tanhP1_kernel(const float2* __restrict__ x,
                   const float*  __restrict__ c2,
                   const float*  __restrict__ c3,
                   const float*  __restrict__ c4,
                   const float*  __restrict__ c5,
                   float2* __restrict__ out,
                   int n2)   // N/2 float2 columns
{
    __shared__ float4 cc[TT];
    for (int i = threadIdx.x; i < TT; i += blockDim.x)
        cc[i] = make_float4(c2[i], c3[i], c4[i], c5[i]);
    __syncthreads();

    const int col = blockIdx.x * blockDim.x + threadIdx.x;
    if (col >= n2) return;

    const float2* xp = x + col;
    float2*       op = out + col;

    // Delay lines: x at time s lives in slot s&7; n1 at time s in slot s&3.
    float xh[8][2];
    float nh[4][2];
#pragma unroll
    for (int i = 0; i < 8; i++) { xh[i][0] = 0.0f; xh[i][1] = 0.0f; }
#pragma unroll
    for (int i = 0; i < 4; i++) { nh[i][0] = 0.0f; nh[i][1] = 0.0f; }

    for (int tb = 0; tb < TT; tb += 8) {
        // ---- front-batch the 8 independent row loads (MLP = 8) ----
        float2 xv[8];
#pragma unroll
        for (int k = 0; k < 8; k++)
            xv[k] = __ldcs(xp + (long)(tb + k) * n2);

        // ---- compute + store the 8 rows ----
#pragma unroll
        for (int k = 0; k < 8; k++) {
            const int t = tb + k;            // t % 8 == k
            const float4 cv = cc[t];

            const int i8 = k;                // x[t-8] slot (then receives x[t])
            const int i4 = (k + 4) & 7;      // x[t-4]
            const int j0 = k & 3;            // n1[t] destination
            const int j1 = (k + 3) & 3;      // n1[t-1]
            const int j2 = (k + 2) & 3;      // n1[t-2]
            const int j3 = (k + 1) & 3;      // n1[t-3]

            float xt[2] = {xv[k].x, xv[k].y};
            float ov[2];
#pragma unroll
            for (int l = 0; l < 2; l++) {
                const float n1  = xt[l] * xh[i4][l];
                const float n2v = 1.0f - n1  * cv.x;
                const float n3  = 1.0f - n2v * (cv.y * nh[j1][l]);
                const float n4v = 1.0f - n3  * (cv.z * nh[j2][l]);
                const float n5  = 1.0f - n4v * (cv.w * nh[j3][l]);
                ov[l] = n5 * xh[i8][l];
                xh[i8][l] = xt[l];
                nh[j0][l] = n1;
            }
            __stcs(op + (long)t * n2, make_float2(ov[0], ov[1]));
        }
    }
}

extern "C" void kernel_launch(void* const* d_in, const int* in_sizes, int n_in,
                              void* d_out, int out_size)
{
    const float* x  = (const float*)d_in[0];
    const float* c2 = (const float*)d_in[1];
    const float* c3 = (const float*)d_in[2];
    const float* c4 = (const float*)d_in[3];
    const float* c5 = (const float*)d_in[4];

    const int T  = in_sizes[1];           // 256
    const int N  = in_sizes[0] / T;       // 262144
    const int n2 = N / 2;                 // float2 columns

    const int threads = 128;
    dim3 grid((n2 + threads - 1) / threads);
    tanhP1_kernel<<<grid, threads>>>((const float2*)x, c2, c3, c4, c5,
                                     (float2*)d_out, n2);
}

// round 5
// speedup vs baseline: 1.0255x; 1.0255x over previous
#include <cuda_runtime.h>

// tanhP1 bitstream stencil — scalar columns, zero-halo full-T walk.
// out[t] = n5 * x[t-8]:
//   n1 = x[t]*x[t-4]
//   n2 = 1 - n1*c2[t]
//   n3 = 1 - n2*c3[t]*n1[t-1]
//   n4 = 1 - n3*c4[t]*n1[t-2]
//   n5 = 1 - n4*c5[t]*n1[t-3]
// Exact {0,1} floats -> FFMA arithmetic is bit-exact.
//
// Round-5 changes vs round-4:
//  * one float column per thread (2x threads = 262144 -> ~48 warps/SM
//    resident; R4 was grid-limited at ~28 warps/SM which cost 9% of BW)
//  * registers drop further (delay lines halve) -> occupancy cap rises
//  * keeps: zero halo (512 MB compulsory traffic), MLP=8 front-batched
//    loads, __ldcs/__stcs streaming hints, shared c-table

#define TT 256

__global__ __launch_bounds__(256)
void tanhP1_kernel(const float* __restrict__ x,
                   const float* __restrict__ c2,
                   const float* __restrict__ c3,
                   const float* __restrict__ c4,
                   const float* __restrict__ c5,
                   float* __restrict__ out,
                   int n)    // N columns
{
    __shared__ float4 cc[TT];
    for (int i = threadIdx.x; i < TT; i += blockDim.x)
        cc[i] = make_float4(c2[i], c3[i], c4[i], c5[i]);
    __syncthreads();

    const int col = blockIdx.x * blockDim.x + threadIdx.x;
    if (col >= n) return;

    const float* xp = x + col;
    float*       op = out + col;

    // Delay lines: x at time s lives in slot s&7; n1 at time s in slot s&3.
    float xh[8];
    float nh[4];
#pragma unroll
    for (int i = 0; i < 8; i++) xh[i] = 0.0f;
#pragma unroll
    for (int i = 0; i < 4; i++) nh[i] = 0.0f;

    for (int tb = 0; tb < TT; tb += 8) {
        // ---- front-batch the 8 independent row loads (MLP = 8) ----
        float xv[8];
#pragma unroll
        for (int k = 0; k < 8; k++)
            xv[k] = __ldcs(xp + (long)(tb + k) * n);

        // ---- compute + store the 8 rows ----
#pragma unroll
        for (int k = 0; k < 8; k++) {
            const int t = tb + k;            // t % 8 == k
            const float4 cv = cc[t];

            const int i8 = k;                // x[t-8] slot (then receives x[t])
            const int i4 = (k + 4) & 7;      // x[t-4]
            const int j0 = k & 3;            // n1[t] destination
            const int j1 = (k + 3) & 3;      // n1[t-1]
            const int j2 = (k + 2) & 3;      // n1[t-2]
            const int j3 = (k + 1) & 3;      // n1[t-3]

            const float n1  = xv[k] * xh[i4];
            const float n2v = 1.0f - n1  * cv.x;
            const float n3  = 1.0f - n2v * (cv.y * nh[j1]);
            const float n4v = 1.0f - n3  * (cv.z * nh[j2]);
            const float n5  = 1.0f - n4v * (cv.w * nh[j3]);
            const float ov  = n5 * xh[i8];
            xh[i8] = xv[k];
            nh[j0] = n1;

            __stcs(op + (long)t * n, ov);
        }
    }
}

extern "C" void kernel_launch(void* const* d_in, const int* in_sizes, int n_in,
                              void* d_out, int out_size)
{
    const float* x  = (const float*)d_in[0];
    const float* c2 = (const float*)d_in[1];
    const float* c3 = (const float*)d_in[2];
    const float* c4 = (const float*)d_in[3];
    const float* c5 = (const float*)d_in[4];

    const int T = in_sizes[1];            // 256
    const int N = in_sizes[0] / T;        // 262144

    const int threads = 256;
    dim3 grid((N + threads - 1) / threads);
    tanhP1_kernel<<<grid, threads>>>(x, c2, c3, c4, c5, (float*)d_out, N);
}